// round 5
// baseline (speedup 1.0000x reference)
#include <cuda_runtime.h>
#include <cstdint>

// Problem constants (fixed by the reference)
#define H            8
#define NUM_DRAM     4096
#define NUM_HBM      819          // int(4096 * 0.2)
#define TOPK         256
#define PAGE_SIZE    16
#define HEAD_DIM     128
#define PAGE_ELEMS   4096         // 16 * 2 * 128
#define SEQ_PER_HEAD (NUM_HBM * PAGE_SIZE)              // 13104
#define KELEMS_HEAD  ((size_t)SEQ_PER_HEAD * HEAD_DIM)  // 1,677,312
#define KTOTAL       ((size_t)H * KELEMS_HEAD)          // 13,418,496

// ---------------------------------------------------------------------------
// ONE fused kernel. One block per (head, hbm_slot) page; each block
// redundantly derives the LRU decision FOR ITS OWN SLOT ONLY, then copies.
//
// Reference semantics emulated exactly, incl. JAX negative-index WRAPPING in
// scatters (idx=-1 -> slot 818, applied before mode='drop'):
//   slot = d2h[topk];  pat[slot>=0 ? slot : 818] = step_f
//   stable rank(i) over pat;  slot i is a victim iff rank(i) < n_miss,
//   receiving the page of the rank(i)-th miss (inverse of order[] scatter).
//   Hits scatter to wrapped slot 818, last hit wins (818 is never a victim:
//   pat[818]==step_f puts its rank above any possible n_miss).
//
// Control inputs (pat 26KB, d2h 128KB, topk 8KB) are L2-resident after the
// first wave, so the per-block replication is ~35MB of L2 hits — noise next
// to the 214MB DRAM copy.
// ---------------------------------------------------------------------------
__global__ void __launch_bounds__(256) lru_fused_kernel(
    const float* __restrict__ dram,
    const float* __restrict__ hbm,
    const float* __restrict__ pat_g,
    const int*   __restrict__ d2h_g,
    const int*   __restrict__ topk_g,
    const int*   __restrict__ step_g,
    float*       __restrict__ kout,
    float*       __restrict__ vout)
{
    __shared__ float pat_s[NUM_HBM];
    __shared__ int   miss_page[TOPK];
    __shared__ int   warp_pre[TOPK / 32];
    __shared__ int   n_miss_s, last_hit_s, last_hit_page_s, src_page_s;

    const int page_id = blockIdx.x;            // 0 .. H*NUM_HBM-1
    const int h = page_id / NUM_HBM;
    const int s = page_id - h * NUM_HBM;
    const int t    = threadIdx.x;              // 0..255
    const int warp = t >> 5;
    const int lane = t & 31;
    const float step_f = (float)(step_g[0] + 1);

    if (t == 0) { last_hit_s = -1; last_hit_page_s = -1; }

    for (int i = t; i < NUM_HBM; i += 256)
        pat_s[i] = pat_g[h * NUM_HBM + i];

    // Every thread owns one topk entry
    const int p    = topk_g[h * TOPK + t];
    const int slot = d2h_g[h * NUM_DRAM + p];
    const bool miss = (slot < 0);
    const unsigned m = __ballot_sync(0xFFFFFFFFu, miss);
    const int wpre = __popc(m & ((1u << lane) - 1u));
    if (lane == 0) warp_pre[warp] = __popc(m);
    if (!miss) atomicMax(&last_hit_s, t);
    __syncthreads();

    // pat scatter with wrapped negative index (all writes = step_f; races benign)
    pat_s[miss ? (NUM_HBM - 1) : slot] = step_f;
    if (t == 0) {                         // scan 8 warp miss-counts
        int c = 0;
        #pragma unroll
        for (int w = 0; w < TOPK / 32; w++) { const int x = warp_pre[w]; warp_pre[w] = c; c += x; }
        n_miss_s = c;
    }
    __syncthreads();

    if (miss) miss_page[warp_pre[warp] + wpre] = p;
    if (t == last_hit_s) last_hit_page_s = p;
    __syncthreads();

    // Warp 0: stable rank of THIS block's slot s, then the src-page decision
    if (warp == 0) {
        const float vi = pat_s[s];
        int r = 0;
        #pragma unroll 2
        for (int j = lane; j < NUM_HBM; j += 32) {
            const float vj = pat_s[j];
            r += (vj < vi) || (vj == vi && j < s);
        }
        r = __reduce_add_sync(0xFFFFFFFFu, r);
        if (lane == 0) {
            int sp = (r < n_miss_s) ? miss_page[r] : -1;
            if (s == NUM_HBM - 1 && last_hit_page_s >= 0) sp = last_hit_page_s;
            src_page_s = sp;
        }
    }
    __syncthreads();

    // ---- Bulk de-interleaving copy (unchanged: at the DRAM roofline) ----
    const int sp = src_page_s;
    const float4* __restrict__ src = (const float4*)(
        (sp >= 0) ? (dram + ((size_t)h * NUM_DRAM + (size_t)sp) * PAGE_ELEMS)
                  : (hbm  + (size_t)page_id * PAGE_ELEMS));

    float4* __restrict__ kbase =
        (float4*)(kout + ((size_t)h * SEQ_PER_HEAD + (size_t)s * PAGE_SIZE) * HEAD_DIM);
    float4* __restrict__ vbase =
        (float4*)(vout + ((size_t)h * SEQ_PER_HEAD + (size_t)s * PAGE_SIZE) * HEAD_DIM);

    // 1024 float4 per page; 4 independent 16B ops per thread (MLP=4).
    #pragma unroll 4
    for (int f = t; f < PAGE_ELEMS / 4; f += 256) {
        const float4 val = src[f];
        const int row = f >> 6;
        const int dd  = f & 31;
        if ((f >> 5) & 1) vbase[row * 32 + dd] = val;
        else              kbase[row * 32 + dd] = val;
    }
}

// ---------------------------------------------------------------------------
// Launch: single kernel, graph-capture friendly, allocation-free.
// ---------------------------------------------------------------------------
extern "C" void kernel_launch(void* const* d_in, const int* in_sizes, int n_in,
                              void* d_out, int out_size)
{
    const float* dram = (const float*)d_in[0];   // (H, 4096, 4096) f32
    const float* hbm  = (const float*)d_in[1];   // (H, 819, 4096)  f32
    const float* pat  = (const float*)d_in[2];   // (H, 819)        f32
    const int*   d2h  = (const int*)  d_in[3];   // (H, 4096)       i32
    // d_in[4] = h2d (never affects the returned k/v caches)
    const int*   topk = (const int*)  d_in[5];   // (H, 256)        i32
    const int*   step = (const int*)  d_in[6];   // (1,)            i32

    float* kout = (float*)d_out;
    float* vout = (float*)d_out + KTOTAL;

    lru_fused_kernel<<<H * NUM_HBM, 256>>>(dram, hbm, pat, d2h, topk, step, kout, vout);
}

// round 6
// speedup vs baseline: 1.0258x; 1.0258x over previous
#include <cuda_runtime.h>
#include <cstdint>

// Problem constants (fixed by the reference)
#define H            8
#define NUM_DRAM     4096
#define NUM_HBM      819          // int(4096 * 0.2)
#define TOPK         256
#define PAGE_SIZE    16
#define HEAD_DIM     128
#define PAGE_ELEMS   4096         // 16 * 2 * 128
#define SEQ_PER_HEAD (NUM_HBM * PAGE_SIZE)              // 13104
#define KELEMS_HEAD  ((size_t)SEQ_PER_HEAD * HEAD_DIM)  // 1,677,312
#define KTOTAL       ((size_t)H * KELEMS_HEAD)          // 13,418,496

#define SLOTS_PER_WARP 4
#define SLOTS_PER_BLK  128        // 32 warps * 4 slots
#define CHUNKS         ((NUM_HBM + SLOTS_PER_BLK - 1) / SLOTS_PER_BLK)   // 7

// Scratch: for each (head, hbm_slot), the DRAM page to pull in (-1 => keep hbm page)
__device__ int g_src_page[H * NUM_HBM];

// ---------------------------------------------------------------------------
// Setup kernel. grid=(H, 7), block=1024. Each warp ranks 4 slots in ONE sweep.
//
// Emulates the reference exactly, incl. JAX's negative-index WRAPPING in
// scatters (idx=-1 -> slot 818, applied before mode='drop'):
//   slot = d2h[topk];  pat[slot>=0 ? slot : 818] = step_f
//   stable rank(i) over pat;  slot i is a victim iff rank(i) < n_miss,
//   receiving the page of the rank(i)-th miss (inverse of order[] scatter).
//   Hits scatter to wrapped slot 818, last hit wins (818 is never a victim:
//   pat[818]==step_f puts its rank above any possible n_miss).
// ---------------------------------------------------------------------------
__global__ void __launch_bounds__(1024) lru_setup_kernel(
    const float* __restrict__ pat_g,
    const int*   __restrict__ d2h_g,
    const int*   __restrict__ topk_g,
    const int*   __restrict__ step_g)
{
    __shared__ float pat_s[NUM_HBM];
    __shared__ int   topk_s[TOPK];
    __shared__ int   slot_s[TOPK];
    __shared__ int   miss_page[TOPK];
    __shared__ int   warp_pre[TOPK / 32];
    __shared__ int   n_miss_s, last_hit_s, last_hit_page_s;

    const int h    = blockIdx.x;
    const int t    = threadIdx.x;
    const int warp = t >> 5;
    const int lane = t & 31;
    const float step_f = (float)(step_g[0] + 1);

    if (t == 0) { last_hit_s = -1; last_hit_page_s = -1; }
    for (int i = t; i < NUM_HBM; i += 1024)
        pat_s[i] = pat_g[h * NUM_HBM + i];

    bool miss = false;
    int  wpre = 0;
    if (t < TOPK) {
        const int p = topk_g[h * TOPK + t];
        topk_s[t] = p;
        const int slot = d2h_g[h * NUM_DRAM + p];
        slot_s[t] = slot;
        miss = (slot < 0);
        const unsigned mm = __ballot_sync(0xFFFFFFFFu, miss);
        wpre = __popc(mm & ((1u << lane) - 1u));
        if (lane == 0) warp_pre[warp] = __popc(mm);
        if (!miss) atomicMax(&last_hit_s, t);
    }
    __syncthreads();

    // pat scatter with wrapped negative index (all writes = step_f; races benign)
    if (t < TOPK) pat_s[miss ? (NUM_HBM - 1) : slot_s[t]] = step_f;
    if (t == 0) {
        int c = 0;
        #pragma unroll
        for (int w = 0; w < TOPK / 32; w++) { const int x = warp_pre[w]; warp_pre[w] = c; c += x; }
        n_miss_s = c;
    }
    __syncthreads();

    if (t < TOPK && miss) miss_page[warp_pre[warp] + wpre] = topk_s[t];
    if (t == last_hit_s)  last_hit_page_s = topk_s[t];
    __syncthreads();

    // Each warp ranks 4 slots in a single sweep over pat_s.
    const int base = blockIdx.y * SLOTS_PER_BLK + warp;   // slots base, base+32, +64, +96
    float vi[SLOTS_PER_WARP];
    int   r [SLOTS_PER_WARP];
    int   idx[SLOTS_PER_WARP];
    #pragma unroll
    for (int q = 0; q < SLOTS_PER_WARP; q++) {
        idx[q] = base + 32 * q;
        vi[q]  = (idx[q] < NUM_HBM) ? pat_s[idx[q]] : 0.0f;
        r[q]   = 0;
    }
    #pragma unroll 2
    for (int j = lane; j < NUM_HBM; j += 32) {
        const float vj = pat_s[j];
        #pragma unroll
        for (int q = 0; q < SLOTS_PER_WARP; q++)
            r[q] += (vj < vi[q]) || (vj == vi[q] && j < idx[q]);
    }
    #pragma unroll
    for (int q = 0; q < SLOTS_PER_WARP; q++) {
        const int rq = __reduce_add_sync(0xFFFFFFFFu, r[q]);
        if (lane == 0 && idx[q] < NUM_HBM) {
            int sp = (rq < n_miss_s) ? miss_page[rq] : -1;
            if (idx[q] == NUM_HBM - 1 && last_hit_page_s >= 0) sp = last_hit_page_s;
            g_src_page[h * NUM_HBM + idx[q]] = sp;
        }
    }
}

// ---------------------------------------------------------------------------
// Bulk de-interleaving copy. One block per (head, hbm_slot) page.
// Launched with PDL: grid ramps up concurrently with setup; the
// cudaGridDependencySynchronize() orders the g_src_page read after setup.
// ---------------------------------------------------------------------------
__global__ void __launch_bounds__(256) page_copy_kernel(
    const float* __restrict__ dram,
    const float* __restrict__ hbm,
    float*       __restrict__ kout,
    float*       __restrict__ vout)
{
    const int page_id = blockIdx.x;            // 0 .. H*NUM_HBM-1
    const int h = page_id / NUM_HBM;
    const int s = page_id - h * NUM_HBM;

    float4* __restrict__ kbase =
        (float4*)(kout + ((size_t)h * SEQ_PER_HEAD + (size_t)s * PAGE_SIZE) * HEAD_DIM);
    float4* __restrict__ vbase =
        (float4*)(vout + ((size_t)h * SEQ_PER_HEAD + (size_t)s * PAGE_SIZE) * HEAD_DIM);

    cudaGridDependencySynchronize();           // wait for setup results

    const int sp = g_src_page[page_id];
    const float4* __restrict__ src = (const float4*)(
        (sp >= 0) ? (dram + ((size_t)h * NUM_DRAM + (size_t)sp) * PAGE_ELEMS)
                  : (hbm  + (size_t)page_id * PAGE_ELEMS));

    // 1024 float4 per page; 4 independent 16B ops per thread (MLP=4).
    #pragma unroll 4
    for (int f = threadIdx.x; f < PAGE_ELEMS / 4; f += 256) {
        const float4 val = src[f];
        const int row = f >> 6;
        const int dd  = f & 31;
        if ((f >> 5) & 1) vbase[row * 32 + dd] = val;
        else              kbase[row * 32 + dd] = val;
    }
}

// ---------------------------------------------------------------------------
// Launch: setup, then copy with programmatic dependent launch to hide the gap.
// ---------------------------------------------------------------------------
extern "C" void kernel_launch(void* const* d_in, const int* in_sizes, int n_in,
                              void* d_out, int out_size)
{
    const float* dram = (const float*)d_in[0];   // (H, 4096, 4096) f32
    const float* hbm  = (const float*)d_in[1];   // (H, 819, 4096)  f32
    const float* pat  = (const float*)d_in[2];   // (H, 819)        f32
    const int*   d2h  = (const int*)  d_in[3];   // (H, 4096)       i32
    // d_in[4] = h2d (never affects the returned k/v caches)
    const int*   topk = (const int*)  d_in[5];   // (H, 256)        i32
    const int*   step = (const int*)  d_in[6];   // (1,)            i32

    float* kout = (float*)d_out;
    float* vout = (float*)d_out + KTOTAL;

    lru_setup_kernel<<<dim3(H, CHUNKS), 1024>>>(pat, d2h, topk, step);

    cudaLaunchConfig_t cfg = {};
    cfg.gridDim  = dim3(H * NUM_HBM);
    cfg.blockDim = dim3(256);
    cfg.dynamicSmemBytes = 0;
    cfg.stream = 0;
    cudaLaunchAttribute attrs[1];
    attrs[0].id = cudaLaunchAttributeProgrammaticStreamSerialization;
    attrs[0].val.programmaticStreamSerializationAllowed = 1;
    cfg.attrs = attrs;
    cfg.numAttrs = 1;
    cudaLaunchKernelEx(&cfg, page_copy_kernel, dram, hbm, kout, vout);
}